// round 2
// baseline (speedup 1.0000x reference)
#include <cuda_runtime.h>
#include <stdint.h>

// ---------------------------------------------------------------------------
// Spiking ConvNet + STDP, T=32, B=32. fp32 throughout, reference-exact forms.
// ---------------------------------------------------------------------------
#define NB   32
#define N0   115200        // B*60*60   z_on / tp1 (on-channel only)
#define N2   3010560       // B*30*56*56
#define N3   752640        // B*30*28*28
#define N4   1843200       // B*100*24*24

// persistent state (__device__ globals: allowed scratch)
__device__ float d_zon[N0];
__device__ float d_tp1[N0];
__device__ unsigned char d_z2b[N2];
__device__ float d_v0[N2];
__device__ float d_i0[N2];
__device__ float d_tq1[N2];
__device__ unsigned char d_z3b[N3];
__device__ float d_tp2[N3];
__device__ unsigned char d_act1[NB*30];
__device__ unsigned char d_z4b[N4];
__device__ float d_v1[N4];
__device__ float d_i1[N4];
__device__ float d_tq2[N4];
__device__ float d_w1[1500];
__device__ float d_wdiff[750];
__device__ float d_w2[75000];
__device__ float d_fc1T[3200*500];
__device__ float d_g[3200];
__device__ float d_pH[NB*500];
__device__ float d_p1P[NB*30*25];
__device__ float d_p1M[NB*30*25];
__device__ float d_p2P[NB*75000];
__device__ float d_p2M[NB*75000];
__device__ float d_v2[500];
__device__ float d_i2[500];
__device__ float d_vo[10];
__device__ float d_io[10];
__device__ float d_g1k[25];
__device__ float d_g2k[25];

// ---------------------------------------------------------------------------
__global__ void k_init(const float* __restrict__ w1, const float* __restrict__ w2)
{
    int i = blockIdx.x * blockDim.x + threadIdx.x;
    if (i < 75000) d_w2[i] = w2[i];
    if (i < 1500)  d_w1[i] = w1[i];
    if (i < 750) {
        int co = i / 25, k = i % 25;
        d_wdiff[i] = w1[co*50 + k] - w1[co*50 + 25 + k];
    }
    if (i < 500) { d_v2[i] = 0.f; d_i2[i] = 0.f; }
    if (i < 10)  { d_vo[i] = 0.f; d_io[i] = 0.f; }
    if (i == 0) {
        float e1[25], e2[25], s1 = 0.f, s2 = 0.f;
        for (int a = 0; a < 25; a++) {
            int yy = a/5 - 2, xx = a%5 - 2;
            float r2 = (float)(yy*yy + xx*xx);
            e1[a] = expf(-r2 * 0.5f);   s1 += e1[a];
            e2[a] = expf(-r2 * 0.125f); s2 += e2[a];
        }
        for (int a = 0; a < 25; a++) { d_g1k[a] = e1[a]/s1; d_g2k[a] = e2[a]/s2; }
    }
}

__global__ void k_tr(const float* __restrict__ fc1w)
{
    int idx = blockIdx.x * 256 + threadIdx.x;   // 1,600,000
    int i = idx / 500, j = idx % 500;
    d_fc1T[idx] = fc1w[j*3200 + i];
}

__global__ void k_zero()
{
    int i = blockIdx.x * 1024 + threadIdx.x;    // grid 2940 -> covers N2 exactly
    if (i < N2) { d_v0[i] = 0.f; d_i0[i] = 0.f; d_tq1[i] = 0.f; }
    if (i < N4) { d_v1[i] = 0.f; d_i1[i] = 0.f; d_tq2[i] = 0.f; }
    if (i < N0) d_tp1[i] = 0.f;
    if (i < N3) d_tp2[i] = 0.f;
}

// ---------------------------------------------------------------------------
// spikes from OLD state (+ post-trace updates)
__global__ void k_lif0()
{
    int i = blockIdx.x * 1024 + threadIdx.x;    // N2 exact
    float v = d_v0[i], cur = d_i0[i];
    float vdec = v + 0.1f * (cur - v);
    float z = (vdec - 15.0f > 0.0f) ? 1.0f : 0.0f;
    d_v0[i] = (1.0f - z) * vdec;
    d_z2b[i] = (unsigned char)z;
    float tq = d_tq1[i];
    d_tq1[i] = tq + 0.02f * (z - tq);
}

__global__ void k_lif1()
{
    int i = blockIdx.x * 1024 + threadIdx.x;    // N4 exact
    float v = d_v1[i], cur = d_i1[i];
    float vdec = v + 0.1f * (cur - v);
    float z = (vdec - 10.0f > 0.0f) ? 1.0f : 0.0f;
    d_v1[i] = (1.0f - z) * vdec;
    d_z4b[i] = (unsigned char)z;
    float tq = d_tq2[i];
    d_tq2[i] = tq + 0.02f * (z - tq);
}

// DoG on-channel + pre-trace
__global__ void k_dog(const float* __restrict__ x, const float* __restrict__ b1p,
                      const float* __restrict__ b2p, int t)
{
    int b = blockIdx.x;
    int p = blockIdx.y * 900 + threadIdx.x;     // 3600
    int y = p / 60, xq = p % 60;
    const float* xp = x + (long)(t*NB + b) * 4096;
    float s1 = 0.f, s2 = 0.f;
    #pragma unroll
    for (int kh = 0; kh < 5; kh++)
        #pragma unroll
        for (int kw = 0; kw < 5; kw++) {
            float v = xp[(y+kh)*64 + xq + kw];
            s1 = fmaf(v, d_g1k[kh*5+kw], s1);
            s2 = fmaf(v, d_g2k[kh*5+kw], s2);
        }
    float z = (s1 + b1p[0]) - (s2 + b2p[0]);
    int idx = b * 3600 + p;
    d_zon[idx] = z;
    float tp = d_tp1[idx];
    d_tp1[idx] = tp + 0.02f * (z - tp);
}

// conv1 + i0 decay/update
__global__ void k_conv1()
{
    __shared__ float zons[3600];
    int b = blockIdx.x, co = blockIdx.y, tid = threadIdx.x;
    for (int i = tid; i < 3600; i += 512) zons[i] = d_zon[b*3600 + i];
    float wd[25];
    #pragma unroll
    for (int k = 0; k < 25; k++) wd[k] = d_wdiff[co*25 + k];
    __syncthreads();
    int base = (b*30 + co) * 3136;
    for (int p = tid; p < 3136; p += 512) {
        int oy = p / 56, ox = p % 56;
        float acc = 0.f;
        #pragma unroll
        for (int kh = 0; kh < 5; kh++)
            #pragma unroll
            for (int kw = 0; kw < 5; kw++)
                acc = fmaf(zons[(oy+kh)*60 + ox + kw], wd[kh*5+kw], acc);
        float cur = d_i0[base + p];
        d_i0[base + p] = (cur - 0.2f*cur) + acc;
    }
}

// maxpool -> z3, tp2 trace, per-(b,ci) activity flag
__global__ void k_maxpool()
{
    int b = blockIdx.x, ci = blockIdx.y, tid = threadIdx.x;
    int bc = b*30 + ci;
    const unsigned char* zsrc = d_z2b + bc*3136;
    int anyf = 0;
    for (int p = tid; p < 784; p += 256) {
        int y = p / 28, xq = p % 28;
        const unsigned char* zp = zsrc + (2*y)*56 + 2*xq;
        unsigned char z = (unsigned char)(zp[0] | zp[1] | zp[56] | zp[57]);
        d_z3b[bc*784 + p] = z;
        anyf |= z;
        float zf = (float)z;
        float tp = d_tp2[bc*784 + p];
        d_tp2[bc*784 + p] = tp + 0.02f * (zf - tp);
    }
    int any = __syncthreads_or(anyf);
    if (tid == 0) d_act1[bc] = (unsigned char)(any ? 1 : 0);
}

// conv2 (binary z3): grid (B, 13 groups of 8 co), block 192 (3 pos/thread)
__global__ void k_conv2()
{
    __shared__ float ws[8*750];
    __shared__ uint32_t z3su[5880];
    __shared__ unsigned char acts[32];
    unsigned char* z3s = (unsigned char*)z3su;
    int b = blockIdx.x, coB = blockIdx.y * 8, tid = threadIdx.x;
    for (int i = tid; i < 6000; i += 192) {
        int c = i / 750;
        ws[i] = (coB + c < 100) ? d_w2[(coB + c)*750 + (i % 750)] : 0.0f;
    }
    const uint32_t* z3g = (const uint32_t*)(d_z3b + b*23520);
    for (int i = tid; i < 5880; i += 192) z3su[i] = z3g[i];
    if (tid < 30) acts[tid] = d_act1[b*30 + tid];
    __syncthreads();

    int p0 = tid * 3;
    int rb0 = (p0/24)*28 + (p0%24);
    int rb1 = ((p0+1)/24)*28 + ((p0+1)%24);
    int rb2 = ((p0+2)/24)*28 + ((p0+2)%24);
    float acc0[8] = {0,0,0,0,0,0,0,0};
    float acc1[8] = {0,0,0,0,0,0,0,0};
    float acc2[8] = {0,0,0,0,0,0,0,0};

    for (int ci = 0; ci < 30; ci++) {
        if (!acts[ci]) continue;
        const unsigned char* zp = z3s + ci*784;
        const float* wt = ws + ci*25;
        #pragma unroll
        for (int kh = 0; kh < 5; kh++) {
            #pragma unroll
            for (int kw = 0; kw < 5; kw++) {
                int off = kh*28 + kw;
                unsigned z0 = zp[rb0 + off], z1 = zp[rb1 + off], z2 = zp[rb2 + off];
                if (__ballot_sync(0xffffffffu, z0 | z1 | z2) == 0) continue;
                float f0 = (float)z0, f1 = (float)z1, f2 = (float)z2;
                #pragma unroll
                for (int c = 0; c < 8; c++) {
                    float w = wt[c*750 + kh*5 + kw];
                    acc0[c] = fmaf(f0, w, acc0[c]);
                    acc1[c] = fmaf(f1, w, acc1[c]);
                    acc2[c] = fmaf(f2, w, acc2[c]);
                }
            }
        }
    }
    #pragma unroll
    for (int c = 0; c < 8; c++) {
        if (coB + c >= 100) break;
        int base = (b*100 + coB + c) * 576;
        float cur;
        cur = d_i1[base + p0];     d_i1[base + p0]     = (cur - 0.2f*cur) + 10.0f*acc0[c];
        cur = d_i1[base + p0 + 1]; d_i1[base + p0 + 1] = (cur - 0.2f*cur) + 10.0f*acc1[c];
        cur = d_i1[base + p0 + 2]; d_i1[base + p0 + 2] = (cur - 0.2f*cur) + 10.0f*acc2[c];
    }
}

// g = any(z4 plane) per (b,co)
__global__ void k_g()
{
    int bc = blockIdx.x, tid = threadIdx.x;
    uint32_t w = 0;
    if (tid < 144) w = ((const uint32_t*)d_z4b)[bc*144 + tid];
    int any = __syncthreads_or(w != 0u);
    if (tid == 0) d_g[bc] = any ? 1.0f : 0.0f;
}

// fc partials per b (binary g gating, uniform branch)
__global__ void k_fc()
{
    int b = blockIdx.x, j = threadIdx.x;
    if (j >= 500) return;
    float acc = 0.f;
    for (int co = 0; co < 100; co++) {
        float gv = d_g[b*100 + co];
        if (gv != 0.0f) acc += d_fc1T[(b*100 + co)*500 + j];
    }
    d_pH[b*500 + j] = acc;
}

// head: combine fc, lif2, LI output cell, write voltages[t]
__global__ void k_head(const float* __restrict__ fc1b, const float* __restrict__ outw,
                       float* __restrict__ out, int t)
{
    __shared__ float zs[500];
    __shared__ float vos[10];
    int j = threadIdx.x;
    if (j < 500) {
        float s = fc1b[j];
        #pragma unroll 4
        for (int b = 0; b < NB; b++) s += d_pH[b*500 + j];
        float v = d_v2[j], cur = d_i2[j];
        float vdec = v + 0.1f * (cur - v);
        float z = (vdec - 1.0f > 0.0f) ? 1.0f : 0.0f;
        d_v2[j] = (1.0f - z) * vdec;
        d_i2[j] = (cur - 0.2f*cur) + s;
        zs[j] = z;
    }
    __syncthreads();
    if (j < 10) {
        float acc = 0.f;
        for (int k = 0; k < 500; k++)
            if (zs[k] != 0.0f) acc += outw[j*500 + k];
        float ij = d_io[j] + acc;
        float vo = d_vo[j];
        vo = vo + 0.1f * (ij - vo);
        d_vo[j] = vo;
        d_io[j] = ij - 0.2f*ij;
        vos[j] = vo;
    }
    __syncthreads();
    if (j < 320) out[t*320 + j] = vos[j % 10];
}

// STDP1 correlations per (b,co): accP gated by z2 spikes, accM dense
__global__ void k_stdp1()
{
    __shared__ float zons[3600];
    __shared__ float tp1s[3600];
    int b = blockIdx.x, co = blockIdx.y, tid = threadIdx.x;
    int bc = b*30 + co;
    for (int i = tid; i < 3600; i += 128) { zons[i] = d_zon[b*3600+i]; tp1s[i] = d_tp1[b*3600+i]; }
    __syncthreads();
    float accP[25], accM[25];
    #pragma unroll
    for (int q = 0; q < 25; q++) { accP[q] = 0.f; accM[q] = 0.f; }
    const float* tq1g = d_tq1 + bc*3136;
    const unsigned char* z2g = d_z2b + bc*3136;
    for (int k = 0; k < 25; k++) {
        int p = tid + k*128;
        bool val = p < 3136;
        float tqv = val ? tq1g[p] : 0.f;
        unsigned char zb = val ? z2g[p] : (unsigned char)0;
        int base = val ? (p/56)*60 + (p%56) : 0;
        #pragma unroll
        for (int kh = 0; kh < 5; kh++)
            #pragma unroll
            for (int kw = 0; kw < 5; kw++)
                accM[kh*5+kw] = fmaf(zons[base + kh*60 + kw], tqv, accM[kh*5+kw]);
        if (__ballot_sync(0xffffffffu, zb)) {
            float zf = (float)zb;
            #pragma unroll
            for (int kh = 0; kh < 5; kh++)
                #pragma unroll
                for (int kw = 0; kw < 5; kw++)
                    accP[kh*5+kw] = fmaf(zf, tp1s[base + kh*60 + kw], accP[kh*5+kw]);
        }
    }
    __syncthreads();                 // done with zons; reuse as reduction buffer
    float* red = zons;               // needs 200 floats
    int lane = tid & 31, wrp = tid >> 5;
    #pragma unroll
    for (int q = 0; q < 25; q++) {
        float v = accP[q];
        for (int o = 16; o > 0; o >>= 1) v += __shfl_down_sync(0xffffffffu, v, o);
        if (lane == 0) red[q*4 + wrp] = v;
        float m = accM[q];
        for (int o = 16; o > 0; o >>= 1) m += __shfl_down_sync(0xffffffffu, m, o);
        if (lane == 0) red[100 + q*4 + wrp] = m;
    }
    __syncthreads();
    if (tid < 50) {
        int q = tid;
        const float* src = (q < 25) ? (red + q*4) : (red + 100 + (q-25)*4);
        float s = src[0] + src[1] + src[2] + src[3];
        if (q < 25) d_p1P[bc*25 + q] = s;
        else        d_p1M[bc*25 + (q-25)] = s;
    }
}

__global__ void k_w1up()
{
    int t = threadIdx.x;
    if (t >= 750) return;
    int co = t / 25, k = t % 25;
    float sp = 0.f, sm = 0.f;
    for (int b = 0; b < NB; b++) {
        sp += d_p1P[(b*30 + co)*25 + k];
        sm += d_p1M[(b*30 + co)*25 + k];
    }
    float w0 = d_w1[co*50 + k];
    float w1v = d_w1[co*50 + 25 + k];
    float n0 = (w0 + 0.004f*fmaxf(1.f - w0, 0.f)*sp) - 0.003f*fmaxf(w0, 0.f)*sm;
    n0 = fminf(fmaxf(n0, 0.f), 1.f);
    float n1 = (w1v + 0.004f*fmaxf(1.f - w1v, 0.f)*(-sp)) - 0.003f*fmaxf(w1v, 0.f)*(-sm);
    n1 = fminf(fmaxf(n1, 0.f), 1.f);
    d_w1[co*50 + k] = n0;
    d_w1[co*50 + 25 + k] = n1;
    d_wdiff[t] = n0 - n1;
}

// STDP2 correlations: grid (B, 10 groups of 10 co), block 768 (taps)
__global__ void k_stdp2()
{
    __shared__ uint32_t z3su[5880];
    __shared__ uint32_t z4m[576];
    __shared__ float tq2s[10*576];
    unsigned char* z3s = (unsigned char*)z3su;
    int b = blockIdx.x, coB = blockIdx.y * 10, tid = threadIdx.x;
    const uint32_t* z3g = (const uint32_t*)(d_z3b + b*23520);
    for (int i = tid; i < 5880; i += 768) z3su[i] = z3g[i];
    for (int p = tid; p < 576; p += 768) {
        uint32_t m = 0;
        #pragma unroll
        for (int c = 0; c < 10; c++)
            m |= (d_z4b[(b*100 + coB + c)*576 + p] ? 1u : 0u) << c;
        z4m[p] = m;
    }
    for (int i = tid; i < 5760; i += 768) {
        int c = i / 576, p = i % 576;
        tq2s[i] = d_tq2[(b*100 + coB + c)*576 + p];
    }
    __syncthreads();

    int t = (tid < 750) ? tid : 749;
    int ci = t / 25, kh = (t % 25) / 5, kw = t % 5;
    int off = kh*28 + kw;
    const unsigned char* zrow = z3s + ci*784;
    const float* tp2g = d_tp2 + (b*30 + ci)*784;
    float accP[10], accM[10];
    #pragma unroll
    for (int c = 0; c < 10; c++) { accP[c] = 0.f; accM[c] = 0.f; }

    int rowbase = 0, ox = 0;
    for (int p = 0; p < 576; p++) {
        int sh = rowbase + off;
        uint32_t m = z4m[p];
        unsigned char zb = zrow[sh];
        unsigned anyM = __ballot_sync(0xffffffffu, zb);
        if (m) {
            float tpv = __ldg(tp2g + sh);
            #pragma unroll
            for (int c = 0; c < 10; c++)
                if ((m >> c) & 1u) accP[c] += tpv;
        }
        if (anyM) {
            float zf = (float)zb;
            #pragma unroll
            for (int c = 0; c < 10; c++)
                accM[c] = fmaf(zf, tq2s[c*576 + p], accM[c]);
        }
        rowbase++; ox++;
        if (ox == 24) { ox = 0; rowbase += 4; }
    }
    if (tid < 750) {
        #pragma unroll
        for (int c = 0; c < 10; c++) {
            d_p2P[(b*100 + coB + c)*750 + t] = accP[c];
            d_p2M[(b*100 + coB + c)*750 + t] = accM[c];
        }
    }
}

__global__ void k_w2up()
{
    int idx = blockIdx.x * 256 + threadIdx.x;
    if (idx >= 75000) return;
    float sp = 0.f, sm = 0.f;
    for (int b = 0; b < NB; b++) {
        sp += d_p2P[b*75000 + idx];
        sm += d_p2M[b*75000 + idx];
    }
    float w = d_w2[idx];
    float n = (w + 0.004f*fmaxf(1.f - w, 0.f)*sp) - 0.003f*fmaxf(w, 0.f)*sm;
    d_w2[idx] = fminf(fmaxf(n, 0.f), 1.f);
}

// ---------------------------------------------------------------------------
extern "C" void kernel_launch(void* const* d_in, const int* in_sizes, int n_in,
                              void* d_out, int out_size)
{
    const float* x    = (const float*)d_in[0];
    const float* b1   = (const float*)d_in[1];
    const float* b2   = (const float*)d_in[2];
    const float* w1   = (const float*)d_in[3];
    const float* w2   = (const float*)d_in[4];
    const float* fc1w = (const float*)d_in[5];
    const float* fc1b = (const float*)d_in[6];
    const float* outw = (const float*)d_in[7];
    float* out = (float*)d_out;

    k_init<<<294, 256>>>(w1, w2);
    k_tr<<<6250, 256>>>(fc1w);
    k_zero<<<2940, 1024>>>();

    for (int t = 0; t < 32; t++) {
        k_lif0<<<2940, 1024>>>();
        k_lif1<<<1800, 1024>>>();
        k_dog<<<dim3(32, 4), 900>>>(x, b1, b2, t);
        k_conv1<<<dim3(32, 30), 512>>>();
        k_maxpool<<<dim3(32, 30), 256>>>();
        k_conv2<<<dim3(32, 13), 192>>>();
        k_g<<<3200, 160>>>();
        k_fc<<<32, 512>>>();
        k_head<<<1, 512>>>(fc1b, outw, out, t);
        k_stdp1<<<dim3(32, 30), 128>>>();
        k_w1up<<<1, 768>>>();
        k_stdp2<<<dim3(32, 10), 768>>>();
        k_w2up<<<294, 256>>>();
    }
}

// round 10
// speedup vs baseline: 2.2092x; 2.2092x over previous
#include <cuda_runtime.h>
#include <stdint.h>

// ---------------------------------------------------------------------------
// Spiking ConvNet + STDP, T=32, B=32. fp32 throughout, reference-exact forms.
// Round 3 fused pipeline (resubmit #7): fused LIF/pool/trace kernels,
// sparse-list STDP2. 9 kernels/step.
// ---------------------------------------------------------------------------
#define NB   32
#define N0   115200        // B*60*60   z_on / tp1 (on-channel only)
#define N2   3010560       // B*30*56*56
#define N3   752640        // B*30*28*28
#define N4   1843200       // B*100*24*24

__device__ float d_zon[N0];
__device__ float d_tp1[N0];
__device__ unsigned char d_z2b[N2];
__device__ float d_v0[N2];
__device__ float d_i0[N2];
__device__ float d_tq1[N2];
__device__ unsigned char d_z3b[N3];
__device__ float d_tp2[N3];
__device__ unsigned char d_act1[NB*30];
__device__ unsigned char d_z4b[N4];
__device__ float d_v1[N4];
__device__ float d_i1[N4];
__device__ float d_tq2[N4];
__device__ float d_w1[1500];
__device__ float d_wdiff[750];
__device__ float d_w2[75000];
__device__ float d_fc1T[3200*500];
__device__ float d_g[3200];
__device__ float d_pH[NB*500];
__device__ float d_p1P[NB*30*25];
__device__ float d_p1M[NB*30*25];
__device__ float d_p2P[NB*75000];
__device__ float d_p2M[NB*75000];
__device__ float d_v2[500];
__device__ float d_i2[500];
__device__ float d_vo[10];
__device__ float d_io[10];
__device__ float d_g1k[25];
__device__ float d_g2k[25];

// ---------------------------------------------------------------------------
__global__ void k_init(const float* __restrict__ w1, const float* __restrict__ w2)
{
    int i = blockIdx.x * blockDim.x + threadIdx.x;
    if (i < 75000) d_w2[i] = w2[i];
    if (i < 1500)  d_w1[i] = w1[i];
    if (i < 750) {
        int co = i / 25, k = i % 25;
        d_wdiff[i] = w1[co*50 + k] - w1[co*50 + 25 + k];
    }
    if (i < 500) { d_v2[i] = 0.f; d_i2[i] = 0.f; }
    if (i < 10)  { d_vo[i] = 0.f; d_io[i] = 0.f; }
    if (i == 0) {
        float e1[25], e2[25], s1 = 0.f, s2 = 0.f;
        for (int a = 0; a < 25; a++) {
            int yy = a/5 - 2, xx = a%5 - 2;
            float r2 = (float)(yy*yy + xx*xx);
            e1[a] = expf(-r2 * 0.5f);   s1 += e1[a];
            e2[a] = expf(-r2 * 0.125f); s2 += e2[a];
        }
        for (int a = 0; a < 25; a++) { d_g1k[a] = e1[a]/s1; d_g2k[a] = e2[a]/s2; }
    }
}

__global__ void k_tr(const float* __restrict__ fc1w)
{
    int idx = blockIdx.x * 256 + threadIdx.x;   // 1,600,000
    int i = idx / 500, j = idx % 500;
    d_fc1T[idx] = fc1w[j*3200 + i];
}

__global__ void k_zero()
{
    int i = blockIdx.x * 1024 + threadIdx.x;
    if (i < N2) { d_v0[i] = 0.f; d_i0[i] = 0.f; d_tq1[i] = 0.f; }
    if (i < N4) { d_v1[i] = 0.f; d_i1[i] = 0.f; d_tq2[i] = 0.f; }
    if (i < N0) d_tp1[i] = 0.f;
    if (i < N3) d_tp2[i] = 0.f;
}

// ---------------------------------------------------------------------------
// DoG on-channel + pre-trace
__global__ void k_dog(const float* __restrict__ x, const float* __restrict__ b1p,
                      const float* __restrict__ b2p, int t)
{
    int b = blockIdx.x;
    int p = blockIdx.y * 900 + threadIdx.x;     // 3600
    int y = p / 60, xq = p % 60;
    const float* xp = x + (long)(t*NB + b) * 4096;
    float s1 = 0.f, s2 = 0.f;
    #pragma unroll
    for (int kh = 0; kh < 5; kh++)
        #pragma unroll
        for (int kw = 0; kw < 5; kw++) {
            float v = xp[(y+kh)*64 + xq + kw];
            s1 = fmaf(v, d_g1k[kh*5+kw], s1);
            s2 = fmaf(v, d_g2k[kh*5+kw], s2);
        }
    float z = (s1 + b1p[0]) - (s2 + b2p[0]);
    int idx = b * 3600 + p;
    d_zon[idx] = z;
    float tp = d_tp1[idx];
    d_tp1[idx] = tp + 0.02f * (z - tp);
}

// conv1 + LIF0 spike (pre-update state) + i0 update + maxpool + tp2 + act flag
__global__ void k_conv1f()
{
    __shared__ float zons[3600];
    __shared__ unsigned char z2s[3136];
    int b = blockIdx.x, co = blockIdx.y, tid = threadIdx.x;
    for (int i = tid; i < 3600; i += 512) zons[i] = d_zon[b*3600 + i];
    float wd[25];
    #pragma unroll
    for (int k = 0; k < 25; k++) wd[k] = d_wdiff[co*25 + k];
    __syncthreads();
    int base = (b*30 + co) * 3136;
    for (int p = tid; p < 3136; p += 512) {
        int oy = p / 56, ox = p % 56;
        float acc = 0.f;
        #pragma unroll
        for (int kh = 0; kh < 5; kh++)
            #pragma unroll
            for (int kw = 0; kw < 5; kw++)
                acc = fmaf(zons[(oy+kh)*60 + ox + kw], wd[kh*5+kw], acc);
        float v = d_v0[base + p], cur = d_i0[base + p];
        float vdec = v + 0.1f * (cur - v);
        float z = (vdec - 15.0f > 0.0f) ? 1.0f : 0.0f;
        d_v0[base + p] = (1.0f - z) * vdec;
        unsigned char zb = (unsigned char)z;
        z2s[p] = zb;
        d_z2b[base + p] = zb;
        d_i0[base + p] = (cur - 0.2f*cur) + acc;
    }
    __syncthreads();
    int bc = b*30 + co;
    int anyf = 0;
    for (int p = tid; p < 784; p += 512) {
        int y = p / 28, xq = p % 28;
        const unsigned char* zp = z2s + (2*y)*56 + 2*xq;
        unsigned char z = (unsigned char)(zp[0] | zp[1] | zp[56] | zp[57]);
        d_z3b[bc*784 + p] = z;
        anyf |= z;
        float zf = (float)z;
        float tp = d_tp2[bc*784 + p];
        d_tp2[bc*784 + p] = tp + 0.02f * (zf - tp);
    }
    int any = __syncthreads_or(anyf);
    if (tid == 0) d_act1[bc] = (unsigned char)(any ? 1 : 0);
}

// conv2 (binary z3) + LIF1 spike + i1 update + per-channel g flag
__global__ void k_conv2f()
{
    __shared__ float ws[8*750];
    __shared__ uint32_t z3su[5880];
    __shared__ unsigned char acts[32];
    unsigned char* z3s = (unsigned char*)z3su;
    int b = blockIdx.x, coB = blockIdx.y * 8, tid = threadIdx.x;
    for (int i = tid; i < 6000; i += 192) {
        int c = i / 750;
        ws[i] = (coB + c < 100) ? d_w2[(coB + c)*750 + (i % 750)] : 0.0f;
    }
    const uint32_t* z3g = (const uint32_t*)(d_z3b + b*23520);
    for (int i = tid; i < 5880; i += 192) z3su[i] = z3g[i];
    if (tid < 30) acts[tid] = d_act1[b*30 + tid];
    __syncthreads();

    int p0 = tid * 3;
    int rb0 = (p0/24)*28 + (p0%24);
    int rb1 = ((p0+1)/24)*28 + ((p0+1)%24);
    int rb2 = ((p0+2)/24)*28 + ((p0+2)%24);
    float acc0[8] = {0,0,0,0,0,0,0,0};
    float acc1[8] = {0,0,0,0,0,0,0,0};
    float acc2[8] = {0,0,0,0,0,0,0,0};

    for (int ci = 0; ci < 30; ci++) {
        if (!acts[ci]) continue;
        const unsigned char* zp = z3s + ci*784;
        const float* wt = ws + ci*25;
        #pragma unroll
        for (int kh = 0; kh < 5; kh++) {
            #pragma unroll
            for (int kw = 0; kw < 5; kw++) {
                int off = kh*28 + kw;
                unsigned z0 = zp[rb0 + off], z1 = zp[rb1 + off], z2 = zp[rb2 + off];
                if (__ballot_sync(0xffffffffu, z0 | z1 | z2) == 0) continue;
                float f0 = (float)z0, f1 = (float)z1, f2 = (float)z2;
                #pragma unroll
                for (int c = 0; c < 8; c++) {
                    float w = wt[c*750 + kh*5 + kw];
                    acc0[c] = fmaf(f0, w, acc0[c]);
                    acc1[c] = fmaf(f1, w, acc1[c]);
                    acc2[c] = fmaf(f2, w, acc2[c]);
                }
            }
        }
    }
    // fused LIF1 epilogue
    int sp[8];
    #pragma unroll
    for (int c = 0; c < 8; c++) {
        sp[c] = 0;
        if (coB + c < 100) {
            int base = (b*100 + coB + c) * 576;
            float av[3] = {acc0[c], acc1[c], acc2[c]};
            #pragma unroll
            for (int q = 0; q < 3; q++) {
                int p = p0 + q;
                float v = d_v1[base + p], cur = d_i1[base + p];
                float vdec = v + 0.1f * (cur - v);
                float z = (vdec - 10.0f > 0.0f) ? 1.0f : 0.0f;
                d_v1[base + p] = (1.0f - z) * vdec;
                d_z4b[base + p] = (unsigned char)z;
                d_i1[base + p] = (cur - 0.2f*cur) + 10.0f*av[q];
                sp[c] |= (int)z;
            }
        }
    }
    #pragma unroll
    for (int c = 0; c < 8; c++) {
        int a = __syncthreads_or(sp[c]);
        if (tid == 0 && coB + c < 100) d_g[b*100 + coB + c] = a ? 1.0f : 0.0f;
    }
}

// fc partials per b (binary g gating, uniform branch)
__global__ void k_fc()
{
    int b = blockIdx.x, j = threadIdx.x;
    if (j >= 500) return;
    float acc = 0.f;
    #pragma unroll 4
    for (int co = 0; co < 100; co++) {
        float gv = d_g[b*100 + co];
        if (gv != 0.0f) acc += d_fc1T[(b*100 + co)*500 + j];
    }
    d_pH[b*500 + j] = acc;
}

// head: combine fc, lif2, LI output cell, write voltages[t]
__global__ void k_head(const float* __restrict__ fc1b, const float* __restrict__ outw,
                       float* __restrict__ out, int t)
{
    __shared__ float zs[500];
    __shared__ float vos[10];
    int j = threadIdx.x;
    if (j < 500) {
        float s = fc1b[j];
        #pragma unroll 4
        for (int b = 0; b < NB; b++) s += d_pH[b*500 + j];
        float v = d_v2[j], cur = d_i2[j];
        float vdec = v + 0.1f * (cur - v);
        float z = (vdec - 1.0f > 0.0f) ? 1.0f : 0.0f;
        d_v2[j] = (1.0f - z) * vdec;
        d_i2[j] = (cur - 0.2f*cur) + s;
        zs[j] = z;
    }
    __syncthreads();
    if (j < 320) {
        int o = j >> 5, lane = j & 31;
        float acc = 0.f;
        for (int k = lane; k < 500; k += 32)
            if (zs[k] != 0.0f) acc += outw[o*500 + k];
        #pragma unroll
        for (int s2 = 16; s2 > 0; s2 >>= 1)
            acc += __shfl_down_sync(0xffffffffu, acc, s2);
        if (lane == 0) {
            float ij = d_io[o] + acc;
            float vo = d_vo[o];
            vo = vo + 0.1f * (ij - vo);
            d_vo[o] = vo;
            d_io[o] = ij - 0.2f*ij;
            vos[o] = vo;
        }
    }
    __syncthreads();
    if (j < 320) out[t*320 + j] = vos[j % 10];
}

// STDP1 correlations per (b,co) + fused tq1 post-trace update
__global__ void k_stdp1()
{
    __shared__ float zons[3600];
    __shared__ float tp1s[3600];
    int b = blockIdx.x, co = blockIdx.y, tid = threadIdx.x;
    int bc = b*30 + co;
    for (int i = tid; i < 3600; i += 128) { zons[i] = d_zon[b*3600+i]; tp1s[i] = d_tp1[b*3600+i]; }
    __syncthreads();
    float accP[25], accM[25];
    #pragma unroll
    for (int q = 0; q < 25; q++) { accP[q] = 0.f; accM[q] = 0.f; }
    float* tq1g = d_tq1 + bc*3136;
    const unsigned char* z2g = d_z2b + bc*3136;
    for (int k = 0; k < 25; k++) {
        int p = tid + k*128;
        bool val = p < 3136;
        float tqold = val ? tq1g[p] : 0.f;
        unsigned char zb = val ? z2g[p] : (unsigned char)0;
        float zf = (float)zb;
        float tqv = tqold + 0.02f * (zf - tqold);
        if (val) tq1g[p] = tqv;
        int base = val ? (p/56)*60 + (p%56) : 0;
        #pragma unroll
        for (int kh = 0; kh < 5; kh++)
            #pragma unroll
            for (int kw = 0; kw < 5; kw++)
                accM[kh*5+kw] = fmaf(zons[base + kh*60 + kw], tqv, accM[kh*5+kw]);
        if (__ballot_sync(0xffffffffu, zb)) {
            #pragma unroll
            for (int kh = 0; kh < 5; kh++)
                #pragma unroll
                for (int kw = 0; kw < 5; kw++)
                    accP[kh*5+kw] = fmaf(zf, tp1s[base + kh*60 + kw], accP[kh*5+kw]);
        }
    }
    __syncthreads();
    float* red = zons;               // reuse as reduction buffer (200 floats)
    int lane = tid & 31, wrp = tid >> 5;
    #pragma unroll
    for (int q = 0; q < 25; q++) {
        float v = accP[q];
        for (int o = 16; o > 0; o >>= 1) v += __shfl_down_sync(0xffffffffu, v, o);
        if (lane == 0) red[q*4 + wrp] = v;
        float m = accM[q];
        for (int o = 16; o > 0; o >>= 1) m += __shfl_down_sync(0xffffffffu, m, o);
        if (lane == 0) red[100 + q*4 + wrp] = m;
    }
    __syncthreads();
    if (tid < 50) {
        int q = tid;
        const float* src = (q < 25) ? (red + q*4) : (red + 100 + (q-25)*4);
        float s = src[0] + src[1] + src[2] + src[3];
        if (q < 25) d_p1P[bc*25 + q] = s;
        else        d_p1M[bc*25 + (q-25)] = s;
    }
}

__global__ void k_w1up()
{
    int t = threadIdx.x;
    if (t >= 750) return;
    int co = t / 25, k = t % 25;
    float sp = 0.f, sm = 0.f;
    for (int b = 0; b < NB; b++) {
        sp += d_p1P[(b*30 + co)*25 + k];
        sm += d_p1M[(b*30 + co)*25 + k];
    }
    float w0 = d_w1[co*50 + k];
    float w1v = d_w1[co*50 + 25 + k];
    float n0 = (w0 + 0.004f*fmaxf(1.f - w0, 0.f)*sp) - 0.003f*fmaxf(w0, 0.f)*sm;
    n0 = fminf(fmaxf(n0, 0.f), 1.f);
    float n1 = (w1v + 0.004f*fmaxf(1.f - w1v, 0.f)*(-sp)) - 0.003f*fmaxf(w1v, 0.f)*(-sm);
    n1 = fminf(fmaxf(n1, 0.f), 1.f);
    d_w1[co*50 + k] = n0;
    d_w1[co*50 + 25 + k] = n1;
    d_wdiff[t] = n0 - n1;
}

// STDP2 correlations + fused tq2 update; sparse z4 list for P, act-gated M
__global__ void k_stdp2()
{
    __shared__ uint32_t z3su[5880];
    __shared__ uint32_t z4m[576];
    __shared__ float tq2s[10*576];
    __shared__ unsigned char acts[32];
    __shared__ int s_list[576];
    __shared__ int s_n;
    unsigned char* z3s = (unsigned char*)z3su;
    int b = blockIdx.x, coB = blockIdx.y * 10, tid = threadIdx.x;
    const uint32_t* z3g = (const uint32_t*)(d_z3b + b*23520);
    for (int i = tid; i < 5880; i += 768) z3su[i] = z3g[i];
    for (int p = tid; p < 576; p += 768) {
        uint32_t m = 0;
        #pragma unroll
        for (int c = 0; c < 10; c++)
            m |= (d_z4b[(b*100 + coB + c)*576 + p] ? 1u : 0u) << c;
        z4m[p] = m;
    }
    for (int i = tid; i < 5760; i += 768) {
        int c = i / 576, p = i % 576;
        int gi = (b*100 + coB + c)*576 + p;
        float tq = d_tq2[gi];
        float zf = d_z4b[gi] ? 1.0f : 0.0f;
        float tn = tq + 0.02f * (zf - tq);
        d_tq2[gi] = tn;
        tq2s[i] = tn;
    }
    if (tid < 30) acts[tid] = d_act1[b*30 + tid];
    __syncthreads();

    // warp 0: compact active z4 positions (deterministic ascending order)
    if (tid < 32) {
        int cnt = 0;
        for (int base = 0; base < 576; base += 32) {
            int p = base + tid;
            unsigned m = z4m[p];
            unsigned bal = __ballot_sync(0xffffffffu, m != 0u);
            if (m) {
                int rank = __popc(bal & ((1u << tid) - 1u));
                s_list[cnt + rank] = p;
            }
            cnt += __popc(bal);
        }
        if (tid == 0) s_n = cnt;
    }
    __syncthreads();

    int t = (tid < 750) ? tid : 749;
    int ci = t / 25, kh = (t % 25) / 5, kw = t % 5;
    int off = kh*28 + kw;
    const unsigned char* zrow = z3s + ci*784;
    const float* tp2g = d_tp2 + (b*30 + ci)*784;
    float accP[10], accM[10];
    #pragma unroll
    for (int c = 0; c < 10; c++) { accP[c] = 0.f; accM[c] = 0.f; }

    // P loop: only active z4 positions (block-uniform)
    int nact = s_n;
    for (int idx = 0; idx < nact; idx++) {
        int p = s_list[idx];
        unsigned m = z4m[p];
        int sh = (p/24)*28 + (p%24) + off;
        float tpv = __ldg(tp2g + sh);
        #pragma unroll
        for (int c = 0; c < 10; c++)
            if ((m >> c) & 1u) accP[c] += tpv;
    }

    // M loop: skip whole warp if its input planes are silent
    int w0tap = tid & ~31;
    int ciLo = w0tap / 25;
    int ciHi = ((w0tap + 31 < 750) ? (w0tap + 31) : 749) / 25;
    int wact = 0;
    for (int cc = ciLo; cc <= ciHi; cc++) wact |= acts[cc];
    if (wact) {
        int rowbase = 0, ox = 0;
        for (int p = 0; p < 576; p++) {
            unsigned char zb = zrow[rowbase + off];
            if (__ballot_sync(0xffffffffu, zb)) {
                float zf = (float)zb;
                #pragma unroll
                for (int c = 0; c < 10; c++)
                    accM[c] = fmaf(zf, tq2s[c*576 + p], accM[c]);
            }
            rowbase++; ox++;
            if (ox == 24) { ox = 0; rowbase += 4; }
        }
    }
    if (tid < 750) {
        #pragma unroll
        for (int c = 0; c < 10; c++) {
            d_p2P[(b*100 + coB + c)*750 + t] = accP[c];
            d_p2M[(b*100 + coB + c)*750 + t] = accM[c];
        }
    }
}

__global__ void k_w2up()
{
    int idx = blockIdx.x * 256 + threadIdx.x;
    if (idx >= 75000) return;
    float sp = 0.f, sm = 0.f;
    for (int b = 0; b < NB; b++) {
        sp += d_p2P[b*75000 + idx];
        sm += d_p2M[b*75000 + idx];
    }
    float w = d_w2[idx];
    float n = (w + 0.004f*fmaxf(1.f - w, 0.f)*sp) - 0.003f*fmaxf(w, 0.f)*sm;
    d_w2[idx] = fminf(fmaxf(n, 0.f), 1.f);
}

// ---------------------------------------------------------------------------
extern "C" void kernel_launch(void* const* d_in, const int* in_sizes, int n_in,
                              void* d_out, int out_size)
{
    const float* x    = (const float*)d_in[0];
    const float* b1   = (const float*)d_in[1];
    const float* b2   = (const float*)d_in[2];
    const float* w1   = (const float*)d_in[3];
    const float* w2   = (const float*)d_in[4];
    const float* fc1w = (const float*)d_in[5];
    const float* fc1b = (const float*)d_in[6];
    const float* outw = (const float*)d_in[7];
    float* out = (float*)d_out;

    k_init<<<294, 256>>>(w1, w2);
    k_tr<<<6250, 256>>>(fc1w);
    k_zero<<<2940, 1024>>>();

    for (int t = 0; t < 32; t++) {
        k_dog<<<dim3(32, 4), 900>>>(x, b1, b2, t);
        k_conv1f<<<dim3(32, 30), 512>>>();
        k_conv2f<<<dim3(32, 13), 192>>>();
        k_fc<<<32, 512>>>();
        k_head<<<1, 512>>>(fc1b, outw, out, t);
        k_stdp1<<<dim3(32, 30), 128>>>();
        k_w1up<<<1, 768>>>();
        k_stdp2<<<dim3(32, 10), 768>>>();
        k_w2up<<<294, 256>>>();
    }
}